// round 7
// baseline (speedup 1.0000x reference)
#include <cuda_runtime.h>
#include <cooperative_groups.h>

namespace cg = cooperative_groups;

#define K 7
#define HH 1024
#define WW 1024
#define NBINS (K * K)
#define NCTAS 8
#define TPB 1024
#define NWARPS (TPB / 32)
#define FINAL_RANK 7

__device__ __forceinline__ void bin_extents(float ci, float cj, float h, float w,
                                            int bi, int bj,
                                            int& r0, int& r1, int& c0, int& c1) {
    // Mirror the reference float32 arithmetic.
    float i0 = ci - h * 0.5f, i1 = ci + h * 0.5f;
    float j0 = cj - w * 0.5f, j1 = cj + w * 0.5f;
    float stepi = (i1 - i0) / (float)(K + 1);
    float stepj = (j1 - j0) / (float)(K + 1);
    float ic = i0 + (float)(bi + 1) * stepi;
    float jc = j0 + (float)(bj + 1) * stepj;
    float bh2 = h / (float)K * 0.5f;
    float bw2 = w / (float)K * 0.5f;
    r0 = (int)floorf((ic - bh2) * (float)HH);
    r1 = (int)ceilf ((ic + bh2) * (float)HH);
    c0 = (int)floorf((jc - bw2) * (float)WW);
    c1 = (int)ceilf ((jc + bw2) * (float)WW);
    r0 = max(r0, 0); r1 = min(r1, HH);
    c0 = max(c0, 0); c1 = min(c1, WW);
}

__global__ void __cluster_dims__(NCTAS, 1, 1) __launch_bounds__(TPB)
psroi_cluster_kernel(const float* __restrict__ x,
                     const float* __restrict__ region,
                     float* __restrict__ out) {
    cg::cluster_group cluster = cg::this_cluster();
    const unsigned rank = cluster.block_rank();
    const int t    = threadIdx.x;
    const int wid  = t >> 5;
    const int lane = t & 31;

    __shared__ float s[NWARPS];
    __shared__ float partials[NCTAS];   // only used on FINAL_RANK

    const float4 reg = *reinterpret_cast<const float4*>(region);

    // accumulate all of this CTA's bins, pre-scaled by 1/(count*49),
    // into one register accumulator (deterministic fixed loop order)
    float acc = 0.0f;
    for (int bin = (int)rank; bin < NBINS; bin += NCTAS) {
        const int bi = bin / K, bj = bin % K;
        int r0, r1, c0, c1;
        bin_extents(reg.x, reg.y, reg.z, reg.w, bi, bj, r0, r1, c0, c1);

        const float scale = 1.0f / ((float)((r1 - r0) * (c1 - c0)) * (float)NBINS);
        const float* __restrict__ chan = x + (size_t)bin * HH * WW;

        // warp-per-row, lane-per-column: coalesced, no divisions
        for (int r = r0 + wid; r < r1; r += NWARPS) {
            const float* __restrict__ rowp = chan + (size_t)r * WW;
            for (int c = c0 + lane; c < c1; c += 32)
                acc = fmaf(__ldg(rowp + c), scale, acc);
        }
    }

    // block reduce: warp shuffle, then warp 0 over 32 leaders
    #pragma unroll
    for (int o = 16; o > 0; o >>= 1)
        acc += __shfl_down_sync(0xffffffffu, acc, o);
    if (lane == 0) s[wid] = acc;
    __syncthreads();

    if (wid == 0) {
        float v = s[lane];              // NWARPS == 32, all lanes valid
        #pragma unroll
        for (int o = 16; o > 0; o >>= 1)
            v += __shfl_down_sync(0xffffffffu, v, o);
        if (lane == 0) {
            // push partial into FINAL_RANK's smem via DSMEM
            float* dst = cluster.map_shared_rank(&partials[0], FINAL_RANK);
            dst[rank] = v;
        }
    }

    // hardware cluster barrier: release/acquire orders the DSMEM stores
    cluster.sync();

    if (rank == FINAL_RANK && t == 0) {
        float sum = 0.0f;
        #pragma unroll
        for (int i = 0; i < NCTAS; i++)
            sum += partials[i];
        out[0] = sum;
    }
}

extern "C" void kernel_launch(void* const* d_in, const int* in_sizes, int n_in,
                              void* d_out, int out_size) {
    const float* x      = (const float*)d_in[0];
    const float* region = (const float*)d_in[1];
    float* out = (float*)d_out;

    psroi_cluster_kernel<<<NCTAS, TPB>>>(x, region, out);
}

// round 8
// speedup vs baseline: 1.5284x; 1.5284x over previous
#include <cuda_runtime.h>

#define K 7
#define HH 1024
#define WW 1024
#define NBINS (K * K)
#define TPB 256
#define NWARPS (TPB / 32)

// cross-block scratch: float accumulator + release-count (zero-init; consumer resets)
__device__ float        g_sum;
__device__ unsigned int g_count;

__device__ __forceinline__ void red_add_f32_relaxed(float* addr, float v) {
    asm volatile("red.relaxed.gpu.global.add.f32 [%0], %1;" :: "l"(addr), "f"(v) : "memory");
}
__device__ __forceinline__ void red_add_u32_release(unsigned int* addr, unsigned int v) {
    asm volatile("red.release.gpu.global.add.u32 [%0], %1;" :: "l"(addr), "r"(v) : "memory");
}
__device__ __forceinline__ unsigned int ld_acquire_u32(const unsigned int* addr) {
    unsigned int v;
    asm volatile("ld.acquire.gpu.global.u32 %0, [%1];" : "=r"(v) : "l"(addr) : "memory");
    return v;
}
__device__ __forceinline__ float ld_acquire_f32(const float* addr) {
    float v;
    asm volatile("ld.acquire.gpu.global.f32 %0, [%1];" : "=f"(v) : "l"(addr) : "memory");
    return v;
}

__device__ __forceinline__ void bin_extents(float ci, float cj, float h, float w,
                                            int bi, int bj,
                                            int& r0, int& r1, int& c0, int& c1) {
    // Mirror the reference float32 arithmetic.
    float i0 = ci - h * 0.5f, i1 = ci + h * 0.5f;
    float j0 = cj - w * 0.5f, j1 = cj + w * 0.5f;
    float stepi = (i1 - i0) / (float)(K + 1);
    float stepj = (j1 - j0) / (float)(K + 1);
    float ic = i0 + (float)(bi + 1) * stepi;
    float jc = j0 + (float)(bj + 1) * stepj;
    float bh2 = h / (float)K * 0.5f;
    float bw2 = w / (float)K * 0.5f;
    r0 = (int)floorf((ic - bh2) * (float)HH);
    r1 = (int)ceilf ((ic + bh2) * (float)HH);
    c0 = (int)floorf((jc - bw2) * (float)WW);
    c1 = (int)ceilf ((jc + bw2) * (float)WW);
    r0 = max(r0, 0); r1 = min(r1, HH);
    c0 = max(c0, 0); c1 = min(c1, WW);
}

__global__ __launch_bounds__(TPB)
void psroi_pc_kernel(const float* __restrict__ x,
                     const float* __restrict__ region,
                     float* __restrict__ out) {
    const int blk = blockIdx.x;

    // ---------------- consumer block: spins concurrently ----------------
    if (blk == NBINS) {
        if (threadIdx.x == 0) {
            while (ld_acquire_u32(&g_count) < (unsigned)NBINS) { /* spin */ }
            float sum = ld_acquire_f32(&g_sum);
            g_sum   = 0.0f;          // reset for next graph replay
            g_count = 0u;
            out[0] = sum;
        }
        return;
    }

    // ---------------- producer blocks: one bin each ----------------
    const int bin  = blk;            // 0..48
    const int bi   = bin / K, bj = bin % K;
    const int t    = threadIdx.x;
    const int wid  = t >> 5;
    const int lane = t & 31;

    const float4 reg = *reinterpret_cast<const float4*>(region);

    int r0, r1, c0, c1;
    bin_extents(reg.x, reg.y, reg.z, reg.w, bi, bj, r0, r1, c0, c1);

    const int total = (r1 - r0) * (c1 - c0);
    const float* __restrict__ chan = x + (size_t)bin * HH * WW;

    // warp-per-row, lane-per-column gather: coalesced, division-free
    float acc = 0.0f;
    for (int r = r0 + wid; r < r1; r += NWARPS) {
        const float* __restrict__ rowp = chan + (size_t)r * WW;
        for (int c = c0 + lane; c < c1; c += 32)
            acc += __ldg(rowp + c);
    }

    // block reduce: warp shuffle, then warp 0 over 8 leaders
    #pragma unroll
    for (int o = 16; o > 0; o >>= 1)
        acc += __shfl_down_sync(0xffffffffu, acc, o);

    __shared__ float s[NWARPS];
    if (lane == 0) s[wid] = acc;
    __syncthreads();

    if (wid == 0) {
        float v = (lane < NWARPS) ? s[lane] : 0.0f;
        #pragma unroll
        for (int o = 4; o > 0; o >>= 1)
            v += __shfl_down_sync(0xffffffffu, v, o);

        if (lane == 0) {
            // fire-and-forget publish: relaxed float add, then release count
            red_add_f32_relaxed(&g_sum, v / ((float)total * (float)NBINS));
            red_add_u32_release(&g_count, 1u);
        }
    }
}

extern "C" void kernel_launch(void* const* d_in, const int* in_sizes, int n_in,
                              void* d_out, int out_size) {
    const float* x      = (const float*)d_in[0];
    const float* region = (const float*)d_in[1];
    float* out = (float*)d_out;

    psroi_pc_kernel<<<NBINS + 1, TPB>>>(x, region, out);
}

// round 9
// speedup vs baseline: 1.8824x; 1.2316x over previous
#include <cuda_runtime.h>

#define K 7
#define HH 1024
#define WW 1024
#define NBINS (K * K)
#define CHUNKS 16
#define NPROD (NBINS * CHUNKS)     // 784 producer blocks
#define TPB 128
#define NWARPS (TPB / 32)

// cross-block scratch (zero-init; consumer resets each run)
__device__ float        g_sum;
__device__ unsigned int g_count;

__device__ __forceinline__ void red_add_f32_relaxed(float* addr, float v) {
    asm volatile("red.relaxed.gpu.global.add.f32 [%0], %1;" :: "l"(addr), "f"(v) : "memory");
}
__device__ __forceinline__ void red_add_u32_release(unsigned int* addr, unsigned int v) {
    asm volatile("red.release.gpu.global.add.u32 [%0], %1;" :: "l"(addr), "r"(v) : "memory");
}
__device__ __forceinline__ unsigned int ld_acquire_u32(const unsigned int* addr) {
    unsigned int v;
    asm volatile("ld.acquire.gpu.global.u32 %0, [%1];" : "=r"(v) : "l"(addr) : "memory");
    return v;
}
__device__ __forceinline__ float ld_acquire_f32(const float* addr) {
    float v;
    asm volatile("ld.acquire.gpu.global.f32 %0, [%1];" : "=f"(v) : "l"(addr) : "memory");
    return v;
}

__device__ __forceinline__ void bin_extents(float ci, float cj, float h, float w,
                                            int bi, int bj,
                                            int& r0, int& r1, int& c0, int& c1) {
    // Mirror the reference float32 arithmetic.
    float i0 = ci - h * 0.5f, i1 = ci + h * 0.5f;
    float j0 = cj - w * 0.5f, j1 = cj + w * 0.5f;
    float stepi = (i1 - i0) / (float)(K + 1);
    float stepj = (j1 - j0) / (float)(K + 1);
    float ic = i0 + (float)(bi + 1) * stepi;
    float jc = j0 + (float)(bj + 1) * stepj;
    float bh2 = h / (float)K * 0.5f;
    float bw2 = w / (float)K * 0.5f;
    r0 = (int)floorf((ic - bh2) * (float)HH);
    r1 = (int)ceilf ((ic + bh2) * (float)HH);
    c0 = (int)floorf((jc - bw2) * (float)WW);
    c1 = (int)ceilf ((jc + bw2) * (float)WW);
    r0 = max(r0, 0); r1 = min(r1, HH);
    c0 = max(c0, 0); c1 = min(c1, WW);
}

__global__ __launch_bounds__(TPB)
void psroi_pc_kernel(const float* __restrict__ x,
                     const float* __restrict__ region,
                     float* __restrict__ out) {
    // ---------------- consumer: block 0, spins concurrently ----------------
    if (blockIdx.x == 0) {
        if (threadIdx.x == 0) {
            while (ld_acquire_u32(&g_count) < (unsigned)NPROD) { /* spin */ }
            float sum = ld_acquire_f32(&g_sum);
            g_sum   = 0.0f;          // reset for next graph replay
            g_count = 0u;
            out[0] = sum;
        }
        return;
    }

    // ---------------- producers: one (bin, chunk) each ----------------
    const int blk   = blockIdx.x - 1;     // 0..NPROD-1
    const int bin   = blk >> 4;           // /CHUNKS
    const int chunk = blk & (CHUNKS - 1);
    const int bi = bin / K, bj = bin % K;
    const int t    = threadIdx.x;
    const int wid  = t >> 5;
    const int lane = t & 31;

    const float4 reg = *reinterpret_cast<const float4*>(region);

    int r0, r1, c0, c1;
    bin_extents(reg.x, reg.y, reg.z, reg.w, bi, bj, r0, r1, c0, c1);

    const int total = (r1 - r0) * (c1 - c0);    // full-bin count (for scale)
    const int rpc   = (r1 - r0 + CHUNKS - 1) / CHUNKS;
    const int cr0   = r0 + chunk * rpc;
    const int cr1   = min(r1, cr0 + rpc);

    const float* __restrict__ chan = x + (size_t)bin * HH * WW;

    // warp-per-row, lane-per-column: coalesced, division-free, short chains
    float acc = 0.0f;
    for (int r = cr0 + wid; r < cr1; r += NWARPS) {
        const float* __restrict__ rowp = chan + (size_t)r * WW;
        for (int c = c0 + lane; c < c1; c += 32)
            acc += __ldg(rowp + c);
    }

    // block reduce: shuffle within warp, then warp 0 over 4 leaders
    #pragma unroll
    for (int o = 16; o > 0; o >>= 1)
        acc += __shfl_down_sync(0xffffffffu, acc, o);

    __shared__ float s[NWARPS];
    if (lane == 0) s[wid] = acc;
    __syncthreads();

    if (t == 0) {
        float v = s[0];
        #pragma unroll
        for (int i = 1; i < NWARPS; i++) v += s[i];
        // fire-and-forget publish: relaxed float add, then release count
        red_add_f32_relaxed(&g_sum, v / ((float)total * (float)NBINS));
        red_add_u32_release(&g_count, 1u);
    }
}

extern "C" void kernel_launch(void* const* d_in, const int* in_sizes, int n_in,
                              void* d_out, int out_size) {
    const float* x      = (const float*)d_in[0];
    const float* region = (const float*)d_in[1];
    float* out = (float*)d_out;

    psroi_pc_kernel<<<NPROD + 1, TPB>>>(x, region, out);
}